// round 2
// baseline (speedup 1.0000x reference)
#include <cuda_runtime.h>
#include <cstdint>

// ---------------------------------------------------------------------------
// TensorizedEmbedding: vocab 32000 = 8*10*20*20, out 768 = 4*4*6*8,
// ranks (1,16,16,16,1).
//
// Factorize around r2:
//   A^T[d0,d1][r2=16][m01=16]   (80 entries,  80 KB)  <- transposed layout!
//   B  [d2,d3][r2=16][m23=48]   (400 entries, 1.2 MB)
//   out_token[16x48] = A(d0,d1) @ B(d2,d3)   (12288 MACs / token)
//
// v2: zero shared memory. One warp per token. Lane (pg=l>>2, cg=l&3) owns a
// 2-row x 12-col tile (rows {2pg,2pg+1}, cols 4cg+16k+{0..3}, k=0..2).
// Row-paired accumulators via fma.rn.f32x2:
//   acc[h][c] (pair of adjacent cols) += dup(A[r][2pg+h]) * Bpair
// Per warp-r: 1 LDG.64 (A, 64B contiguous -> 1 wf) + 3 LDG.128 (B, 64B
// contiguous, 64B-aligned -> 1 wf each) + 2 dup-packs + 12 FFMA2.
// Output: 6 direct STG.128 per lane, no staging.
// ---------------------------------------------------------------------------

typedef unsigned long long u64;

__device__ __align__(128) float g_A[80 * 256];    //  80 KB  [d0d1][r2][m01]
__device__ __align__(128) float g_B[400 * 768];   // 1.2 MB  [d2d3][r2][m23]

__device__ __forceinline__ u64 pack_dup(float v) {
    u64 r; asm("mov.b64 %0, {%1, %1};" : "=l"(r) : "f"(v)); return r;
}
__device__ __forceinline__ void ffma2(u64& d, u64 a, u64 b) {
    asm("fma.rn.f32x2 %0, %1, %2, %0;" : "+l"(d) : "l"(a), "l"(b));
}
__device__ __forceinline__ void ldg_f2(float& x, float& y, const float* p) {
    asm("ld.global.nc.v2.f32 {%0, %1}, [%2];" : "=f"(x), "=f"(y) : "l"(p));
}
__device__ __forceinline__ void ldg_2u64(u64& x, u64& y, const float* p) {
    asm("ld.global.nc.v2.u64 {%0, %1}, [%2];" : "=l"(x), "=l"(y) : "l"(p));
}
__device__ __forceinline__ void stg_2u64(float* p, u64 x, u64 y) {
    asm("st.global.v2.u64 [%0], {%1, %2};" :: "l"(p), "l"(x), "l"(y) : "memory");
}

// ---------------------------------------------------------------------------
// Precompute both tables. Blocks [0,80) build A^T, [80,480) build B.
// ---------------------------------------------------------------------------
__global__ void __launch_bounds__(768) precompute_kernel(
    const float* __restrict__ c0, const float* __restrict__ c1,
    const float* __restrict__ c2, const float* __restrict__ c3)
{
    int blk = blockIdx.x;
    int t   = threadIdx.x;
    if (blk < 80) {
        if (t >= 256) return;
        int d0 = blk / 10, d1 = blk - d0 * 10;
        int m01 = t >> 4, r2 = t & 15;
        int m0 = m01 >> 2, m1 = m01 & 3;
        float s = 0.f;
        #pragma unroll
        for (int r1 = 0; r1 < 16; ++r1)
            s += c0[(d0 * 4 + m0) * 16 + r1] *
                 c1[((r1 * 10 + d1) * 4 + m1) * 16 + r2];
        g_A[blk * 256 + r2 * 16 + m01] = s;   // transposed: [r2][m01]
    } else {
        int p  = blk - 80;               // 0..399
        int d2 = p / 20, d3 = p - d2 * 20;
        int r2  = t / 48;
        int m23 = t - r2 * 48;
        int m2 = m23 >> 3, m3 = m23 & 7;
        float s = 0.f;
        #pragma unroll
        for (int r3 = 0; r3 < 16; ++r3)
            s += c2[((r2 * 20 + d2) * 6 + m2) * 16 + r3] *
                 c3[(r3 * 20 + d3) * 8 + m3];
        g_B[p * 768 + t] = s;            // [r2][m23]
    }
}

// ---------------------------------------------------------------------------
#define TOK_PER_BLK 8

__global__ void __launch_bounds__(256) embed_kernel(
    const int* __restrict__ x, float* __restrict__ out, int nTok)
{
    int w = threadIdx.x >> 5;
    int l = threadIdx.x & 31;
    int token = blockIdx.x * TOK_PER_BLK + w;
    if (token >= nTok) return;

    int idx = x[token];
    int d0 = idx / 4000; int rem = idx - d0 * 4000;
    int d1 = rem / 400;  rem -= d1 * 400;
    int d2 = rem / 20;   int d3 = rem - d2 * 20;

    const float* Ap = g_A + (d0 * 10 + d1) * 256;   // [r*16 + m01]
    const float* Bp = g_B + (d2 * 20 + d3) * 768;   // [r*48 + m23]

    int pg = l >> 2;     // row-pair: rows {2pg, 2pg+1}
    int cg = l & 3;      // col-quads: cols 4cg+16k+{0..3}, k=0..2

    u64 acc[2][6];       // [row h][col-pair c]; c = 2k, 2k+1
    #pragma unroll
    for (int h = 0; h < 2; ++h)
        #pragma unroll
        for (int c = 0; c < 6; ++c) acc[h][c] = 0ull;

    #pragma unroll
    for (int r = 0; r < 16; ++r) {
        float ax, ay;
        ldg_f2(ax, ay, Ap + r * 16 + pg * 2);        // A[r][2pg], A[r][2pg+1]
        u64 b00, b01, b10, b11, b20, b21;
        const float* brow = Bp + r * 48 + cg * 4;
        ldg_2u64(b00, b01, brow);                    // cols 4cg+0..3
        ldg_2u64(b10, b11, brow + 16);               // cols 4cg+16..19
        ldg_2u64(b20, b21, brow + 32);               // cols 4cg+32..35
        u64 a0 = pack_dup(ax);
        u64 a1 = pack_dup(ay);
        ffma2(acc[0][0], a0, b00); ffma2(acc[0][1], a0, b01);
        ffma2(acc[0][2], a0, b10); ffma2(acc[0][3], a0, b11);
        ffma2(acc[0][4], a0, b20); ffma2(acc[0][5], a0, b21);
        ffma2(acc[1][0], a1, b00); ffma2(acc[1][1], a1, b01);
        ffma2(acc[1][2], a1, b10); ffma2(acc[1][3], a1, b11);
        ffma2(acc[1][4], a1, b20); ffma2(acc[1][5], a1, b21);
    }

    // direct store: 6 STG.128 per lane
    float* op = out + (size_t)token * 768;
    #pragma unroll
    for (int h = 0; h < 2; ++h) {
        float* rowp = op + (pg * 2 + h) * 48 + cg * 4;
        #pragma unroll
        for (int k = 0; k < 3; ++k)
            stg_2u64(rowp + k * 16, acc[h][2 * k], acc[h][2 * k + 1]);
    }
}

// ---------------------------------------------------------------------------
extern "C" void kernel_launch(void* const* d_in, const int* in_sizes, int n_in,
                              void* d_out, int out_size) {
    const int*   x  = (const int*)  d_in[0];
    const float* c0 = (const float*)d_in[1];
    const float* c1 = (const float*)d_in[2];
    const float* c2 = (const float*)d_in[3];
    const float* c3 = (const float*)d_in[4];
    float* out = (float*)d_out;
    int nTok = in_sizes[0];              // 8*4096 = 32768

    precompute_kernel<<<480, 768>>>(c0, c1, c2, c3);

    int grid = (nTok + TOK_PER_BLK - 1) / TOK_PER_BLK;
    embed_kernel<<<grid, 256>>>(x, out, nTok);
}